// round 11
// baseline (speedup 1.0000x reference)
#include <cuda_runtime.h>
#include <math.h>
#include <stdint.h>

#define BATCH 8
#define CHN 128
#define HH 56
#define WW 56
#define TILE_PTS 64
#define NTHREADS 256
#define NTILES 8192
#define GRID_CTAS 148

#define A_STRIDE 260     // 65 x 16B rows: %8==1 -> conflict-free LDSM
#define W1_STRIDE 260
#define WST 68           // stride for W2/W3 stage (%8==4, conflict-free)

// float-index offsets in dynamic smem (two 64-row A buffers back-to-back)
#define FOFF_A     0                          // 2 x 64 x 260
#define FOFF_W1    (128 * A_STRIDE)           // 64 x 260
#define FOFF_MISC  (FOFF_W1 + 64 * W1_STRIDE)
#define MI_B1   0
#define MI_B2   64
#define MI_B3   128
#define MI_W4   192
#define MI_BG   256      // 192 floats
#define MI_PART 448      // 128 floats
#define MISC_FLOATS 640
#define FOFF_W3    (FOFF_MISC + MISC_FLOATS)  // 64 x 68 persistent W3 image
#define SMEM_TOTAL ((FOFF_W3 + 64 * WST) * 4) // ~221 KB

// named barriers: 1,2 = full[b]; 3,4 = empty[b]; 5 = consumer-internal
#define BAR_SYNC256(id) asm volatile("bar.sync %0, 256;" :: "r"(id) : "memory")
#define BAR_ARV256(id)  asm volatile("bar.arrive %0, 256;" :: "r"(id) : "memory")
#define CBAR()          asm volatile("bar.sync 5, 128;" ::: "memory")

// ---------------- globals ----------------
__device__ float g_tf[BATCH * HH * WW * CHN];   // (B,H,W,C) features
__device__ float g_W1T[64 * W1_STRIDE];         // n-major padded tf32 image
__device__ float g_W2Tc[64 * 64];               // compact n-major tf32
__device__ float g_W3Tc[64 * 64];

__device__ __forceinline__ float to_tf32(float x) {
    uint32_t r;
    asm("cvt.rna.tf32.f32 %0, %1;" : "=r"(r) : "f"(x));
    return __uint_as_float(r);
}
__device__ __forceinline__ uint32_t smem_u32(const void* p) {
    uint32_t a;
    asm("{ .reg .u64 t; cvta.to.shared.u64 t, %1; cvt.u32.u64 %0, t; }" : "=r"(a) : "l"(p));
    return a;
}
__device__ __forceinline__ void ldsm4(uint32_t* r, uint32_t addr) {
    asm volatile("ldmatrix.sync.aligned.m8n8.x4.shared.b16 {%0,%1,%2,%3}, [%4];"
                 : "=r"(r[0]), "=r"(r[1]), "=r"(r[2]), "=r"(r[3]) : "r"(addr));
}
__device__ __forceinline__ void mma16n8k8(float* d, const uint32_t* a, uint32_t b0, uint32_t b1) {
    asm volatile(
        "mma.sync.aligned.m16n8k8.row.col.f32.tf32.tf32.f32 "
        "{%0,%1,%2,%3}, {%4,%5,%6,%7}, {%8,%9}, {%0,%1,%2,%3};"
        : "+f"(d[0]), "+f"(d[1]), "+f"(d[2]), "+f"(d[3])
        : "r"(a[0]), "r"(a[1]), "r"(a[2]), "r"(a[3]), "r"(b0), "r"(b1));
}

// ---------------------------------------------------------------------------
// Kernel 1: transpose features + prep weight images (merged)
// ---------------------------------------------------------------------------
__global__ void transpose_kernel(const float* __restrict__ f,
                                 const float* __restrict__ W1,
                                 const float* __restrict__ W2,
                                 const float* __restrict__ W3) {
    __shared__ float tile[32][33];
    const int b  = blockIdx.z;
    const int c0 = blockIdx.y << 5;
    const int s0 = blockIdx.x << 5;
    const int tx = threadIdx.x, ty = threadIdx.y;
    tile[ty][tx] = f[(size_t)(b * CHN + c0 + ty) * 3136 + (s0 + tx)];
    __syncthreads();
    g_tf[(size_t)(b * 3136 + s0 + ty) * CHN + (c0 + tx)] = tile[tx][ty];

    if (blockIdx.x == 0 && blockIdx.y == 0) {
        const int t = ty * 32 + tx;
        const int base = b * 1024 + t;
        for (int i = base; i < 64 * 256; i += 8192) {
            int n = i & 63, k = i >> 6;
            g_W1T[n * W1_STRIDE + k] = to_tf32(W1[k * 64 + n]);
        }
        for (int i = base; i < 64 * 64; i += 8192) {
            int n = i & 63, k = i >> 6;
            g_W2Tc[n * 64 + k] = to_tf32(W2[k * 64 + n]);
            g_W3Tc[n * 64 + k] = to_tf32(W3[k * 64 + n]);
        }
    }
}

// ---------------------------------------------------------------------------
// Kernel 2: warp-specialized persistent decoder
//   warps 0-3: producers (projection + gather + Fourier -> A buffer)
//   warps 4-7: consumers (3 MMA layers + epilogue)
// ---------------------------------------------------------------------------
__global__ __launch_bounds__(NTHREADS, 1)
void decoder_kernel(const float* __restrict__ points,
                    const float* __restrict__ kmat,
                    const float* __restrict__ rtm,
                    const float* __restrict__ Bg,
                    const float* __restrict__ b1,
                    const float* __restrict__ b2,
                    const float* __restrict__ b3,
                    const float* __restrict__ W4,
                    const float* __restrict__ b4,
                    float* __restrict__ out) {
    extern __shared__ float sm[];
    float* sA  = sm + FOFF_A;
    float* sW1 = sm + FOFF_W1;
    float* sW3 = sm + FOFF_W3;
    float* sMi = sm + FOFF_MISC;
    float* sB1 = sMi + MI_B1;
    float* sB2 = sMi + MI_B2;
    float* sB3 = sMi + MI_B3;
    float* sW4 = sMi + MI_W4;
    float* sBg = sMi + MI_BG;
    float* sPart = sMi + MI_PART;

    const int tid  = threadIdx.x;
    const int wid  = tid >> 5;
    const int lane = tid & 31;
    const bool producer = (wid < 4);

    const uint32_t sAu  = smem_u32(sA);
    const uint32_t sW1u = smem_u32(sW1);
    const uint32_t sW3u = smem_u32(sW3);
    const uint32_t BUFOFF = (uint32_t)(64 * A_STRIDE * 4);

    // ---- one-time init (all warps) ----
    {
        const float4* s = (const float4*)g_W1T;
        float4* d = (float4*)sW1;
        for (int i = tid; i < 64 * W1_STRIDE / 4; i += NTHREADS) d[i] = s[i];
    }
    for (int i = tid; i < 64 * 64; i += NTHREADS) {
        int n = i >> 6, k = i & 63;
        sA[n * WST + k]  = g_W2Tc[i];     // temp stage for W2 hoist
        sW3[n * WST + k] = g_W3Tc[i];     // persistent W3 image
    }
    if (tid < 64) {
        sB1[tid] = b1[tid]; sB2[tid] = b2[tid]; sB3[tid] = b3[tid];
        sW4[tid] = W4[tid];
    }
    if (tid < 96) ((float2*)sBg)[tid] = ((const float2*)Bg)[tid];
    const float b4v = b4[0];
    __syncthreads();

    if (producer) {
        // ================= PRODUCER =================
        const int q0 = wid << 4;   // this warp's 16 rows in the buffer
        int it = 0, buf = 0;
        for (int tile = blockIdx.x; tile < NTILES; tile += GRID_CTAS, ++it, buf ^= 1) {
            const int p0 = tile * TILE_PTS;
            const int b  = p0 >> 16;

            // warp-local projection: lanes 0..15 own the warp's 16 points
            float fx = 0.f, fy = 0.f, va = 0.f, ppx = 0.f, ppy = 0.f, ppz = 0.f;
            int x0 = -100000, y0 = -100000;
            if (lane < 16) {
                const float* pt = points + (size_t)(p0 + q0 + lane) * 3;
                ppx = pt[0]; ppy = pt[1]; ppz = pt[2];
                const float* R = rtm + b * 12;
                const float* K = kmat + b * 9;
                const float cx = fmaf(R[0], ppx, fmaf(R[1], ppy, fmaf(R[2],  ppz, R[3])));
                const float cy = fmaf(R[4], ppx, fmaf(R[5], ppy, fmaf(R[6],  ppz, R[7])));
                const float cz = fmaf(R[8], ppx, fmaf(R[9], ppy, fmaf(R[10], ppz, R[11])));
                const float ix = fmaf(K[0], cx, fmaf(K[1], cy, K[2] * cz));
                const float iy = fmaf(K[3], cx, fmaf(K[4], cy, K[5] * cz));
                const float iz = fmaf(K[6], cx, fmaf(K[7], cy, K[8] * cz));
                const bool pos = (iz > 0.0f);
                const float zz = iz + 1e-8f;
                const float u = __fdividef(ix, zz), v = __fdividef(iy, zz);
                const float xf = floorf(u), yf = floorf(v);
                fx = u - xf; fy = v - yf;
                x0 = (int)xf; y0 = (int)yf;
                if (!pos) { x0 = -100000; y0 = -100000; fx = 0.f; fy = 0.f; }
                va = pos ? 1.0f : 0.0f;
            }

            if (it >= 2) BAR_SYNC256(3 + buf);   // wait: buffer freed by consumers

            // merged gather + Fourier into buffer rows
            {
                float* bufbase = sA + buf * 64 * A_STRIDE;
                const float* baseb = g_tf + (size_t)b * 3136 * CHN + lane * 4;
                const float TWOPI = 6.283185307179586f;
                const float bx0 = sBg[lane * 3],        by0 = sBg[lane * 3 + 1],        bz0 = sBg[lane * 3 + 2];
                const float bx1 = sBg[(lane + 32) * 3], by1 = sBg[(lane + 32) * 3 + 1], bz1 = sBg[(lane + 32) * 3 + 2];
#pragma unroll 4
                for (int i = 0; i < 16; ++i) {
                    const float gfx = __shfl_sync(0xffffffffu, fx, i);
                    const float gfy = __shfl_sync(0xffffffffu, fy, i);
                    const float gv  = __shfl_sync(0xffffffffu, va, i);
                    const int   gx  = __shfl_sync(0xffffffffu, x0, i);
                    const int   gy  = __shfl_sync(0xffffffffu, y0, i);
                    const float qx  = __shfl_sync(0xffffffffu, ppx, i);
                    const float qy  = __shfl_sync(0xffffffffu, ppy, i);
                    const float qz  = __shfl_sync(0xffffffffu, ppz, i);

                    const float ax = 1.0f - gfx, ay = 1.0f - gfy;
                    const float w00 = ax * ay * gv;
                    const float w10 = gfx * ay * gv;
                    const float w01 = ax * gfy * gv;
                    const float w11 = gfx * gfy * gv;
                    const bool x0in = (gx >= 0) && (gx < WW);
                    const bool x1in = (gx >= -1) && (gx < WW - 1);
                    const bool y0in = (gy >= 0) && (gy < HH);
                    const bool y1in = (gy >= -1) && (gy < HH - 1);
                    const int rowoff = (gy * WW + gx) * CHN;
                    float4 a4 = make_float4(0.f, 0.f, 0.f, 0.f);
                    if (x0in && y0in) {
                        float4 v4 = *(const float4*)(baseb + rowoff);
                        a4.x = fmaf(w00, v4.x, a4.x); a4.y = fmaf(w00, v4.y, a4.y);
                        a4.z = fmaf(w00, v4.z, a4.z); a4.w = fmaf(w00, v4.w, a4.w);
                    }
                    if (x1in && y0in) {
                        float4 v4 = *(const float4*)(baseb + rowoff + CHN);
                        a4.x = fmaf(w10, v4.x, a4.x); a4.y = fmaf(w10, v4.y, a4.y);
                        a4.z = fmaf(w10, v4.z, a4.z); a4.w = fmaf(w10, v4.w, a4.w);
                    }
                    if (x0in && y1in) {
                        float4 v4 = *(const float4*)(baseb + rowoff + WW * CHN);
                        a4.x = fmaf(w01, v4.x, a4.x); a4.y = fmaf(w01, v4.y, a4.y);
                        a4.z = fmaf(w01, v4.z, a4.z); a4.w = fmaf(w01, v4.w, a4.w);
                    }
                    if (x1in && y1in) {
                        float4 v4 = *(const float4*)(baseb + rowoff + (WW + 1) * CHN);
                        a4.x = fmaf(w11, v4.x, a4.x); a4.y = fmaf(w11, v4.y, a4.y);
                        a4.z = fmaf(w11, v4.z, a4.z); a4.w = fmaf(w11, v4.w, a4.w);
                    }

                    const float xp0 = TWOPI * fmaf(qx, bx0, fmaf(qy, by0, qz * bz0));
                    const float xp1 = TWOPI * fmaf(qx, bx1, fmaf(qy, by1, qz * bz1));
                    float* row = bufbase + (q0 + i) * A_STRIDE;
                    row[128 + lane]      = to_tf32(__sinf(xp0));
                    row[128 + lane + 32] = to_tf32(__sinf(xp1));
                    row[192 + lane]      = to_tf32(__cosf(xp0));
                    row[192 + lane + 32] = to_tf32(__cosf(xp1));

                    a4.x = to_tf32(a4.x); a4.y = to_tf32(a4.y);
                    a4.z = to_tf32(a4.z); a4.w = to_tf32(a4.w);
                    *(float4*)(row + lane * 4) = a4;
                }
            }
            BAR_ARV256(1 + buf);   // buffer full
        }
    } else {
        // ================= CONSUMER =================
        const int cw = wid - 4;
        const int mslot = cw >> 1;
        const int nslot = cw & 1;
        const int gg = lane >> 2;
        const int t  = lane & 3;
        const int ctid = tid - 128;

        const int arow = mslot * 32 + (lane & 15);
        const int acol = (lane >> 4) << 2;
        const uint32_t aB0 = sAu + (uint32_t)((arow * A_STRIDE + acol) << 2);
        const uint32_t aB1 = aB0 + (uint32_t)(16 * A_STRIDE * 4);
        const int nrow = nslot * 32 + ((lane & 16) >> 1) + (lane & 7);
        const int ncol = (lane & 8) ? 4 : 0;
        const uint32_t b1Base0 = sW1u + (uint32_t)((nrow * W1_STRIDE + ncol) << 2);
        const uint32_t b1Base1 = b1Base0 + (uint32_t)(16 * W1_STRIDE * 4);
        const uint32_t w3Base0 = sW3u + (uint32_t)((nrow * WST + ncol) << 2);
        const uint32_t w3Base1 = w3Base0 + (uint32_t)(16 * WST * 4);

        // hoist W2 B-fragments (staged in sA buffer region; consumed before first produce? NO —
        // producers may already be writing buf0. Stage was read AFTER __syncthreads and BEFORE
        // any producer writes buf0 only if we hoist before signaling. Producers write buf0 only
        // after... they don't wait for empty on it=0! So hoist must happen BEFORE __syncthreads
        // releases producers. Use a second __syncthreads fence.)
        uint32_t B2f[64];
        {
            const uint32_t wBase0 = sAu + (uint32_t)((nrow * WST + ncol) << 2);
            const uint32_t wBase1 = wBase0 + (uint32_t)(16 * WST * 4);
#pragma unroll
            for (int kk = 0; kk < 8; ++kk) {
                ldsm4(B2f + kk * 8,     wBase0 + kk * 32);
                ldsm4(B2f + kk * 8 + 4, wBase1 + kk * 32);
            }
        }

        int buf = 0;
        for (int tile = blockIdx.x; tile < NTILES; tile += GRID_CTAS, buf ^= 1) {
            const int p0 = tile * TILE_PTS;
            const uint32_t bo = buf ? BUFOFF : 0u;

            BAR_SYNC256(1 + buf);   // wait: buffer full

            // ===== Layer 1 (pipelined): [64x256] @ W1 =====
            float acc[2][4][4];
#pragma unroll
            for (int mt = 0; mt < 2; ++mt)
#pragma unroll
                for (int nt = 0; nt < 4; ++nt)
#pragma unroll
                    for (int j = 0; j < 4; ++j) acc[mt][nt][j] = 0.0f;
            {
                uint32_t aa0[2][4], aa1[2][4], BB[2][8];
                ldsm4(aa0[0], aB0 + bo);
                ldsm4(aa1[0], aB1 + bo);
                ldsm4(BB[0],     b1Base0);
                ldsm4(BB[0] + 4, b1Base1);
#pragma unroll 2
                for (int kb = 0; kb < 16; ++kb) {
                    const int k1 = 2 * kb + 1;
                    ldsm4(aa0[1], aB0 + bo + k1 * 32);
                    ldsm4(aa1[1], aB1 + bo + k1 * 32);
                    ldsm4(BB[1],     b1Base0 + k1 * 32);
                    ldsm4(BB[1] + 4, b1Base1 + k1 * 32);
#pragma unroll
                    for (int nt = 0; nt < 4; ++nt) {
                        mma16n8k8(acc[0][nt], aa0[0], BB[0][nt * 2], BB[0][nt * 2 + 1]);
                        mma16n8k8(acc[1][nt], aa1[0], BB[0][nt * 2], BB[0][nt * 2 + 1]);
                    }
                    if (kb < 15) {
                        ldsm4(aa0[0], aB0 + bo + (k1 + 1) * 32);
                        ldsm4(aa1[0], aB1 + bo + (k1 + 1) * 32);
                        ldsm4(BB[0],     b1Base0 + (k1 + 1) * 32);
                        ldsm4(BB[0] + 4, b1Base1 + (k1 + 1) * 32);
                    }
#pragma unroll
                    for (int nt = 0; nt < 4; ++nt) {
                        mma16n8k8(acc[0][nt], aa0[1], BB[1][nt * 2], BB[1][nt * 2 + 1]);
                        mma16n8k8(acc[1][nt], aa1[1], BB[1][nt * 2], BB[1][nt * 2 + 1]);
                    }
                }
            }
            CBAR();   // all consumer L1 A-reads done

            // relu(acc + b1) -> buffer cols [0,64)
            float* bufbase = sA + buf * 64 * A_STRIDE;
#pragma unroll
            for (int mt = 0; mt < 2; ++mt) {
                const int r0 = mslot * 32 + mt * 16 + gg;
#pragma unroll
                for (int nt = 0; nt < 4; ++nt) {
                    const int col = nslot * 32 + nt * 8 + t * 2;
                    float2 v0, v1;
                    v0.x = to_tf32(fmaxf(acc[mt][nt][0] + sB1[col], 0.f));
                    v0.y = to_tf32(fmaxf(acc[mt][nt][1] + sB1[col + 1], 0.f));
                    v1.x = to_tf32(fmaxf(acc[mt][nt][2] + sB1[col], 0.f));
                    v1.y = to_tf32(fmaxf(acc[mt][nt][3] + sB1[col + 1], 0.f));
                    *(float2*)(bufbase + r0 * A_STRIDE + col) = v0;
                    *(float2*)(bufbase + (r0 + 8) * A_STRIDE + col) = v1;
                }
            }
            CBAR();   // h1 ready

            // ===== Layer 2 (pipelined A): h1 @ W2, B in regs =====
#pragma unroll
            for (int mt = 0; mt < 2; ++mt)
#pragma unroll
                for (int nt = 0; nt < 4; ++nt)
#pragma unroll
                    for (int j = 0; j < 4; ++j) acc[mt][nt][j] = 0.0f;
            {
                uint32_t aa0[2][4], aa1[2][4];
                ldsm4(aa0[0], aB0 + bo);
                ldsm4(aa1[0], aB1 + bo);
#pragma unroll
                for (int kb = 0; kb < 4; ++kb) {
                    const int k1 = 2 * kb + 1;
                    ldsm4(aa0[1], aB0 + bo + k1 * 32);
                    ldsm4(aa1[1], aB1 + bo + k1 * 32);
#pragma unroll
                    for (int nt = 0; nt < 4; ++nt) {
                        mma16n8k8(acc[0][nt], aa0[0], B2f[(k1 - 1) * 8 + nt * 2], B2f[(k1 - 1) * 8 + nt * 2 + 1]);
                        mma16n8k8(acc[1][nt], aa1[0], B2f[(k1 - 1) * 8 + nt * 2], B2f[(k1 - 1) * 8 + nt * 2 + 1]);
                    }
                    if (kb < 3) {
                        ldsm4(aa0[0], aB0 + bo + (k1 + 1) * 32);
                        ldsm4(aa1[0], aB1 + bo + (k1 + 1) * 32);
                    }
#pragma unroll
                    for (int nt = 0; nt < 4; ++nt) {
                        mma16n8k8(acc[0][nt], aa0[1], B2f[k1 * 8 + nt * 2], B2f[k1 * 8 + nt * 2 + 1]);
                        mma16n8k8(acc[1][nt], aa1[1], B2f[k1 * 8 + nt * 2], B2f[k1 * 8 + nt * 2 + 1]);
                    }
                }
            }
            // relu(acc + b2) -> buffer cols [64,128)  (disjoint from h1 reads)
#pragma unroll
            for (int mt = 0; mt < 2; ++mt) {
                const int r0 = mslot * 32 + mt * 16 + gg;
#pragma unroll
                for (int nt = 0; nt < 4; ++nt) {
                    const int col = nslot * 32 + nt * 8 + t * 2;
                    float2 v0, v1;
                    v0.x = to_tf32(fmaxf(acc[mt][nt][0] + sB2[col], 0.f));
                    v0.y = to_tf32(fmaxf(acc[mt][nt][1] + sB2[col + 1], 0.f));
                    v1.x = to_tf32(fmaxf(acc[mt][nt][2] + sB2[col], 0.f));
                    v1.y = to_tf32(fmaxf(acc[mt][nt][3] + sB2[col + 1], 0.f));
                    *(float2*)(bufbase + r0 * A_STRIDE + 64 + col) = v0;
                    *(float2*)(bufbase + (r0 + 8) * A_STRIDE + 64 + col) = v1;
                }
            }
            CBAR();   // h2 ready

            // ===== Layer 3 (pipelined): h2 @ W3 from smem =====
#pragma unroll
            for (int mt = 0; mt < 2; ++mt)
#pragma unroll
                for (int nt = 0; nt < 4; ++nt)
#pragma unroll
                    for (int j = 0; j < 4; ++j) acc[mt][nt][j] = 0.0f;
            {
                uint32_t aa0[2][4], aa1[2][4], BB[2][8];
                ldsm4(aa0[0], aB0 + bo + 256);
                ldsm4(aa1[0], aB1 + bo + 256);
                ldsm4(BB[0],     w3Base0);
                ldsm4(BB[0] + 4, w3Base1);
#pragma unroll
                for (int kb = 0; kb < 4; ++kb) {
                    const int k1 = 2 * kb + 1;
                    ldsm4(aa0[1], aB0 + bo + 256 + k1 * 32);
                    ldsm4(aa1[1], aB1 + bo + 256 + k1 * 32);
                    ldsm4(BB[1],     w3Base0 + k1 * 32);
                    ldsm4(BB[1] + 4, w3Base1 + k1 * 32);
#pragma unroll
                    for (int nt = 0; nt < 4; ++nt) {
                        mma16n8k8(acc[0][nt], aa0[0], BB[0][nt * 2], BB[0][nt * 2 + 1]);
                        mma16n8k8(acc[1][nt], aa1[0], BB[0][nt * 2], BB[0][nt * 2 + 1]);
                    }
                    if (kb < 3) {
                        ldsm4(aa0[0], aB0 + bo + 256 + (k1 + 1) * 32);
                        ldsm4(aa1[0], aB1 + bo + 256 + (k1 + 1) * 32);
                        ldsm4(BB[0],     w3Base0 + (k1 + 1) * 32);
                        ldsm4(BB[0] + 4, w3Base1 + (k1 + 1) * 32);
                    }
#pragma unroll
                    for (int nt = 0; nt < 4; ++nt) {
                        mma16n8k8(acc[0][nt], aa0[1], BB[1][nt * 2], BB[1][nt * 2 + 1]);
                        mma16n8k8(acc[1][nt], aa1[1], BB[1][nt * 2], BB[1][nt * 2 + 1]);
                    }
                }
            }
            BAR_ARV256(3 + buf);   // buffer empty (A-reads all retired into regs)

            // ---- layer 4 epilogue ----
            {
                float pr[2][2];
                pr[0][0] = pr[0][1] = pr[1][0] = pr[1][1] = 0.0f;
#pragma unroll
                for (int mt = 0; mt < 2; ++mt)
#pragma unroll
                    for (int nt = 0; nt < 4; ++nt) {
                        const int col = nslot * 32 + nt * 8 + t * 2;
                        pr[mt][0] = fmaf(fmaxf(acc[mt][nt][0] + sB3[col], 0.f),     sW4[col],     pr[mt][0]);
                        pr[mt][0] = fmaf(fmaxf(acc[mt][nt][1] + sB3[col + 1], 0.f), sW4[col + 1], pr[mt][0]);
                        pr[mt][1] = fmaf(fmaxf(acc[mt][nt][2] + sB3[col], 0.f),     sW4[col],     pr[mt][1]);
                        pr[mt][1] = fmaf(fmaxf(acc[mt][nt][3] + sB3[col + 1], 0.f), sW4[col + 1], pr[mt][1]);
                    }
#pragma unroll
                for (int mt = 0; mt < 2; ++mt) {
                    pr[mt][0] += __shfl_xor_sync(0xffffffffu, pr[mt][0], 1);
                    pr[mt][0] += __shfl_xor_sync(0xffffffffu, pr[mt][0], 2);
                    pr[mt][1] += __shfl_xor_sync(0xffffffffu, pr[mt][1], 1);
                    pr[mt][1] += __shfl_xor_sync(0xffffffffu, pr[mt][1], 2);
                    if (t == 0) {
                        const int lr = mslot * 32 + mt * 16 + gg;
                        sPart[nslot * 64 + lr] = pr[mt][0];
                        sPart[nslot * 64 + lr + 8] = pr[mt][1];
                    }
                }
            }
            CBAR();   // sPart ready
            if (ctid < 64)
                out[p0 + ctid] = sPart[ctid] + sPart[64 + ctid] + b4v;
            CBAR();   // sPart reads done before next tile overwrites
        }
    }
}

// ---------------------------------------------------------------------------
// Launch
// ---------------------------------------------------------------------------
extern "C" void kernel_launch(void* const* d_in, const int* in_sizes, int n_in,
                              void* d_out, int out_size) {
    const float* features = (const float*)d_in[0];
    const float* points   = (const float*)d_in[1];
    const float* kmat     = (const float*)d_in[2];
    const float* rtm      = (const float*)d_in[3];
    const float* Bg       = (const float*)d_in[4];
    const float* W1 = (const float*)d_in[5];
    const float* b1 = (const float*)d_in[6];
    const float* W2 = (const float*)d_in[7];
    const float* b2 = (const float*)d_in[8];
    const float* W3 = (const float*)d_in[9];
    const float* b3 = (const float*)d_in[10];
    const float* W4 = (const float*)d_in[11];
    const float* b4 = (const float*)d_in[12];

    dim3 tb(32, 32);
    dim3 tg(3136 / 32, CHN / 32, BATCH);
    transpose_kernel<<<tg, tb>>>(features, W1, W2, W3);

    cudaFuncSetAttribute(decoder_kernel,
                         cudaFuncAttributeMaxDynamicSharedMemorySize, SMEM_TOTAL);
    decoder_kernel<<<GRID_CTAS, NTHREADS, SMEM_TOTAL>>>(
        points, kmat, rtm, Bg, b1, b2, b3, W4, b4, (float*)d_out);
}

// round 12
// speedup vs baseline: 1.0330x; 1.0330x over previous
#include <cuda_runtime.h>
#include <math.h>
#include <stdint.h>

#define BATCH 8
#define CHN 128
#define HH 56
#define WW 56
#define TILE_PTS 32
#define NTHREADS 256
#define NTILES 16384
#define GRID_CTAS 148

#define A_STRIDE 260     // 65 x 16B rows: %8==1 -> conflict-free LDSM
#define W1_STRIDE 260
#define WST 68           // stride for W2/W3 stage (%8==4, conflict-free)

// float-index offsets in dynamic smem
#define FOFF_A     0                          // 128 x 260  (4 pairs x 32 rows)
#define FOFF_W1    (128 * A_STRIDE)           // 64 x 260
#define FOFF_MISC  (FOFF_W1 + 64 * W1_STRIDE)
#define MI_B1   0
#define MI_B2   64
#define MI_B3   128
#define MI_W4   192
#define MI_BG   256      // 192 floats
#define MI_PART 448      // 256 floats (4 pairs x 64)
#define MISC_FLOATS 768
#define FOFF_W3    (FOFF_MISC + MISC_FLOATS)  // 64 x 68 persistent W3 image
#define SMEM_TOTAL ((FOFF_W3 + 64 * WST) * 4) // ~222 KB

// pair barrier: named barrier per 64-thread pair (ids 1..4)
#define PBAR() asm volatile("bar.sync %0, 64;" :: "r"(pairid + 1) : "memory")

// ---------------- globals ----------------
__device__ float g_tf[BATCH * HH * WW * CHN];   // (B,H,W,C) features
__device__ float g_W1T[64 * W1_STRIDE];         // n-major padded tf32 image
__device__ float g_W2Tc[64 * 64];               // compact n-major tf32
__device__ float g_W3Tc[64 * 64];

__device__ __forceinline__ float to_tf32(float x) {
    uint32_t r;
    asm("cvt.rna.tf32.f32 %0, %1;" : "=r"(r) : "f"(x));
    return __uint_as_float(r);
}
__device__ __forceinline__ uint32_t smem_u32(const void* p) {
    uint32_t a;
    asm("{ .reg .u64 t; cvta.to.shared.u64 t, %1; cvt.u32.u64 %0, t; }" : "=r"(a) : "l"(p));
    return a;
}
__device__ __forceinline__ void ldsm4(uint32_t* r, uint32_t addr) {
    asm volatile("ldmatrix.sync.aligned.m8n8.x4.shared.b16 {%0,%1,%2,%3}, [%4];"
                 : "=r"(r[0]), "=r"(r[1]), "=r"(r[2]), "=r"(r[3]) : "r"(addr));
}
__device__ __forceinline__ void mma16n8k8(float* d, const uint32_t* a, uint32_t b0, uint32_t b1) {
    asm volatile(
        "mma.sync.aligned.m16n8k8.row.col.f32.tf32.tf32.f32 "
        "{%0,%1,%2,%3}, {%4,%5,%6,%7}, {%8,%9}, {%0,%1,%2,%3};"
        : "+f"(d[0]), "+f"(d[1]), "+f"(d[2]), "+f"(d[3])
        : "r"(a[0]), "r"(a[1]), "r"(a[2]), "r"(a[3]), "r"(b0), "r"(b1));
}

// ---------------------------------------------------------------------------
// Kernel 1: transpose features + prep weight images (merged)
// ---------------------------------------------------------------------------
__global__ void transpose_kernel(const float* __restrict__ f,
                                 const float* __restrict__ W1,
                                 const float* __restrict__ W2,
                                 const float* __restrict__ W3) {
    __shared__ float tile[32][33];
    const int b  = blockIdx.z;
    const int c0 = blockIdx.y << 5;
    const int s0 = blockIdx.x << 5;
    const int tx = threadIdx.x, ty = threadIdx.y;
    tile[ty][tx] = f[(size_t)(b * CHN + c0 + ty) * 3136 + (s0 + tx)];
    __syncthreads();
    g_tf[(size_t)(b * 3136 + s0 + ty) * CHN + (c0 + tx)] = tile[tx][ty];

    if (blockIdx.x == 0 && blockIdx.y == 0) {
        const int t = ty * 32 + tx;
        const int base = b * 1024 + t;
        for (int i = base; i < 64 * 256; i += 8192) {
            int n = i & 63, k = i >> 6;
            g_W1T[n * W1_STRIDE + k] = to_tf32(W1[k * 64 + n]);
        }
        for (int i = base; i < 64 * 64; i += 8192) {
            int n = i & 63, k = i >> 6;
            g_W2Tc[n * 64 + k] = to_tf32(W2[k * 64 + n]);
            g_W3Tc[n * 64 + k] = to_tf32(W3[k * 64 + n]);
        }
    }
}

// ---------------------------------------------------------------------------
// Kernel 2: persistent decoder — 4 independent warp-pairs per CTA
//   pair p = warps {2p, 2p+1}; each pair owns A rows [32p, 32p+32) and
//   processes its own stream of 32-point tiles with 64-thread barriers.
// ---------------------------------------------------------------------------
__global__ __launch_bounds__(NTHREADS, 1)
void decoder_kernel(const float* __restrict__ points,
                    const float* __restrict__ kmat,
                    const float* __restrict__ rtm,
                    const float* __restrict__ Bg,
                    const float* __restrict__ b1,
                    const float* __restrict__ b2,
                    const float* __restrict__ b3,
                    const float* __restrict__ W4,
                    const float* __restrict__ b4,
                    float* __restrict__ out) {
    extern __shared__ float sm[];
    float* sA  = sm + FOFF_A;
    float* sW1 = sm + FOFF_W1;
    float* sW3 = sm + FOFF_W3;
    float* sMi = sm + FOFF_MISC;
    float* sB1 = sMi + MI_B1;
    float* sB2 = sMi + MI_B2;
    float* sB3 = sMi + MI_B3;
    float* sW4 = sMi + MI_W4;
    float* sBg = sMi + MI_BG;
    float* sPart = sMi + MI_PART;

    const int tid  = threadIdx.x;
    const int wid  = tid >> 5;
    const int lane = tid & 31;

    const int pairid = wid >> 1;      // 0..3
    const int nslot  = wid & 1;       // 0..1: cols nslot*32 .. +32
    const int gtid   = tid & 63;      // thread within pair
    const int gg = lane >> 2;
    const int t  = lane & 3;

    const uint32_t sAu  = smem_u32(sA);
    const uint32_t sW1u = smem_u32(sW1);
    const uint32_t sW3u = smem_u32(sW3);

    // A-frag ldsm addresses (two m16 tiles within the pair's 32 rows)
    const int arow = pairid * 32 + (lane & 15);
    const int acol = (lane >> 4) << 2;
    const uint32_t aBase0 = sAu + (uint32_t)((arow * A_STRIDE + acol) << 2);
    const uint32_t aBase1 = aBase0 + (uint32_t)(16 * A_STRIDE * 4);
    // B-frag addresses
    const int nrow = nslot * 32 + ((lane & 16) >> 1) + (lane & 7);
    const int ncol = (lane & 8) ? 4 : 0;
    const uint32_t b1Base0 = sW1u + (uint32_t)((nrow * W1_STRIDE + ncol) << 2);
    const uint32_t b1Base1 = b1Base0 + (uint32_t)(16 * W1_STRIDE * 4);
    const uint32_t w3Base0 = sW3u + (uint32_t)((nrow * WST + ncol) << 2);
    const uint32_t w3Base1 = w3Base0 + (uint32_t)(16 * WST * 4);

    // ---- one-time init ----
    {
        const float4* s = (const float4*)g_W1T;
        float4* d = (float4*)sW1;
        for (int i = tid; i < 64 * W1_STRIDE / 4; i += NTHREADS) d[i] = s[i];
    }
    for (int i = tid; i < 64 * 64; i += NTHREADS) {
        int n = i >> 6, k = i & 63;
        sA[n * WST + k]  = g_W2Tc[i];     // temp stage for W2 hoist
        sW3[n * WST + k] = g_W3Tc[i];     // persistent W3 image
    }
    if (tid < 64) {
        sB1[tid] = b1[tid]; sB2[tid] = b2[tid]; sB3[tid] = b3[tid];
        sW4[tid] = W4[tid];
    }
    if (tid < 96) ((float2*)sBg)[tid] = ((const float2*)Bg)[tid];
    const float b4v = b4[0];
    __syncthreads();

    // hoist W2 B-fragments to registers (from temp stage in sA)
    uint32_t B2f[64];
    {
        const uint32_t wBase0 = sAu + (uint32_t)((nrow * WST + ncol) << 2);
        const uint32_t wBase1 = wBase0 + (uint32_t)(16 * WST * 4);
#pragma unroll
        for (int kk = 0; kk < 8; ++kk) {
            ldsm4(B2f + kk * 8,     wBase0 + kk * 32);
            ldsm4(B2f + kk * 8 + 4, wBase1 + kk * 32);
        }
    }
    __syncthreads();   // stage reads done before any gather overwrites sA

    for (int tile = blockIdx.x * 4 + pairid; tile < NTILES; tile += GRID_CTAS * 4) {
        const int p0 = tile * TILE_PTS;
        const int b  = tile >> 11;        // 2048 tiles of 32 pts per batch

        // ---- warp-local projection: lanes 0..15 own this warp's 16 points ----
        float fx = 0.f, fy = 0.f, va = 0.f, ppx = 0.f, ppy = 0.f, ppz = 0.f;
        int x0 = -100000, y0 = -100000;
        if (lane < 16) {
            const float* pt = points + (size_t)(p0 + nslot * 16 + lane) * 3;
            ppx = pt[0]; ppy = pt[1]; ppz = pt[2];
            const float* R = rtm + b * 12;
            const float* K = kmat + b * 9;
            const float cx = fmaf(R[0], ppx, fmaf(R[1], ppy, fmaf(R[2],  ppz, R[3])));
            const float cy = fmaf(R[4], ppx, fmaf(R[5], ppy, fmaf(R[6],  ppz, R[7])));
            const float cz = fmaf(R[8], ppx, fmaf(R[9], ppy, fmaf(R[10], ppz, R[11])));
            const float ix = fmaf(K[0], cx, fmaf(K[1], cy, K[2] * cz));
            const float iy = fmaf(K[3], cx, fmaf(K[4], cy, K[5] * cz));
            const float iz = fmaf(K[6], cx, fmaf(K[7], cy, K[8] * cz));
            const bool pos = (iz > 0.0f);
            const float zz = iz + 1e-8f;
            const float u = __fdividef(ix, zz), v = __fdividef(iy, zz);
            const float xf = floorf(u), yf = floorf(v);
            fx = u - xf; fy = v - yf;
            x0 = (int)xf; y0 = (int)yf;
            if (!pos) { x0 = -100000; y0 = -100000; fx = 0.f; fy = 0.f; }
            va = pos ? 1.0f : 0.0f;
        }

        // ---- merged gather + Fourier into pair's A rows ----
        {
            const int q0 = pairid * 32 + nslot * 16;
            const float* baseb = g_tf + (size_t)b * 3136 * CHN + lane * 4;
            const float TWOPI = 6.283185307179586f;
            const float bx0 = sBg[lane * 3],        by0 = sBg[lane * 3 + 1],        bz0 = sBg[lane * 3 + 2];
            const float bx1 = sBg[(lane + 32) * 3], by1 = sBg[(lane + 32) * 3 + 1], bz1 = sBg[(lane + 32) * 3 + 2];
#pragma unroll 4
            for (int i = 0; i < 16; ++i) {
                const float gfx = __shfl_sync(0xffffffffu, fx, i);
                const float gfy = __shfl_sync(0xffffffffu, fy, i);
                const float gv  = __shfl_sync(0xffffffffu, va, i);
                const int   gx  = __shfl_sync(0xffffffffu, x0, i);
                const int   gy  = __shfl_sync(0xffffffffu, y0, i);
                const float qx  = __shfl_sync(0xffffffffu, ppx, i);
                const float qy  = __shfl_sync(0xffffffffu, ppy, i);
                const float qz  = __shfl_sync(0xffffffffu, ppz, i);

                const float ax = 1.0f - gfx, ay = 1.0f - gfy;
                const float w00 = ax * ay * gv;
                const float w10 = gfx * ay * gv;
                const float w01 = ax * gfy * gv;
                const float w11 = gfx * gfy * gv;
                const bool x0in = (gx >= 0) && (gx < WW);
                const bool x1in = (gx >= -1) && (gx < WW - 1);
                const bool y0in = (gy >= 0) && (gy < HH);
                const bool y1in = (gy >= -1) && (gy < HH - 1);
                const int rowoff = (gy * WW + gx) * CHN;
                float4 a4 = make_float4(0.f, 0.f, 0.f, 0.f);
                if (x0in && y0in) {
                    float4 v4 = *(const float4*)(baseb + rowoff);
                    a4.x = fmaf(w00, v4.x, a4.x); a4.y = fmaf(w00, v4.y, a4.y);
                    a4.z = fmaf(w00, v4.z, a4.z); a4.w = fmaf(w00, v4.w, a4.w);
                }
                if (x1in && y0in) {
                    float4 v4 = *(const float4*)(baseb + rowoff + CHN);
                    a4.x = fmaf(w10, v4.x, a4.x); a4.y = fmaf(w10, v4.y, a4.y);
                    a4.z = fmaf(w10, v4.z, a4.z); a4.w = fmaf(w10, v4.w, a4.w);
                }
                if (x0in && y1in) {
                    float4 v4 = *(const float4*)(baseb + rowoff + WW * CHN);
                    a4.x = fmaf(w01, v4.x, a4.x); a4.y = fmaf(w01, v4.y, a4.y);
                    a4.z = fmaf(w01, v4.z, a4.z); a4.w = fmaf(w01, v4.w, a4.w);
                }
                if (x1in && y1in) {
                    float4 v4 = *(const float4*)(baseb + rowoff + (WW + 1) * CHN);
                    a4.x = fmaf(w11, v4.x, a4.x); a4.y = fmaf(w11, v4.y, a4.y);
                    a4.z = fmaf(w11, v4.z, a4.z); a4.w = fmaf(w11, v4.w, a4.w);
                }

                const float xp0 = TWOPI * fmaf(qx, bx0, fmaf(qy, by0, qz * bz0));
                const float xp1 = TWOPI * fmaf(qx, bx1, fmaf(qy, by1, qz * bz1));
                float* row = sA + (q0 + i) * A_STRIDE;
                row[128 + lane]      = to_tf32(__sinf(xp0));
                row[128 + lane + 32] = to_tf32(__sinf(xp1));
                row[192 + lane]      = to_tf32(__cosf(xp0));
                row[192 + lane + 32] = to_tf32(__cosf(xp1));

                a4.x = to_tf32(a4.x); a4.y = to_tf32(a4.y);
                a4.z = to_tf32(a4.z); a4.w = to_tf32(a4.w);
                *(float4*)(row + lane * 4) = a4;
            }
        }
        PBAR();   // pair's A rows fully built

        // ================= Layer 1 (pipelined): [32x256] @ W1 =================
        float acc[2][4][4];
#pragma unroll
        for (int mt = 0; mt < 2; ++mt)
#pragma unroll
            for (int nt = 0; nt < 4; ++nt)
#pragma unroll
                for (int j = 0; j < 4; ++j) acc[mt][nt][j] = 0.0f;
        {
            uint32_t aa0[2][4], aa1[2][4], BB[2][8];
            ldsm4(aa0[0], aBase0);
            ldsm4(aa1[0], aBase1);
            ldsm4(BB[0],     b1Base0);
            ldsm4(BB[0] + 4, b1Base1);
#pragma unroll 2
            for (int kb = 0; kb < 16; ++kb) {
                const int k1 = 2 * kb + 1;
                ldsm4(aa0[1], aBase0 + k1 * 32);
                ldsm4(aa1[1], aBase1 + k1 * 32);
                ldsm4(BB[1],     b1Base0 + k1 * 32);
                ldsm4(BB[1] + 4, b1Base1 + k1 * 32);
#pragma unroll
                for (int nt = 0; nt < 4; ++nt) {
                    mma16n8k8(acc[0][nt], aa0[0], BB[0][nt * 2], BB[0][nt * 2 + 1]);
                    mma16n8k8(acc[1][nt], aa1[0], BB[0][nt * 2], BB[0][nt * 2 + 1]);
                }
                if (kb < 15) {
                    ldsm4(aa0[0], aBase0 + (k1 + 1) * 32);
                    ldsm4(aa1[0], aBase1 + (k1 + 1) * 32);
                    ldsm4(BB[0],     b1Base0 + (k1 + 1) * 32);
                    ldsm4(BB[0] + 4, b1Base1 + (k1 + 1) * 32);
                }
#pragma unroll
                for (int nt = 0; nt < 4; ++nt) {
                    mma16n8k8(acc[0][nt], aa0[1], BB[1][nt * 2], BB[1][nt * 2 + 1]);
                    mma16n8k8(acc[1][nt], aa1[1], BB[1][nt * 2], BB[1][nt * 2 + 1]);
                }
            }
        }
        PBAR();   // pair's L1 A-reads done

        // relu(acc + b1) -> A cols [0,64) of pair's rows
#pragma unroll
        for (int mt = 0; mt < 2; ++mt) {
            const int r0 = pairid * 32 + mt * 16 + gg;
#pragma unroll
            for (int nt = 0; nt < 4; ++nt) {
                const int col = nslot * 32 + nt * 8 + t * 2;
                float2 v0, v1;
                v0.x = to_tf32(fmaxf(acc[mt][nt][0] + sB1[col], 0.f));
                v0.y = to_tf32(fmaxf(acc[mt][nt][1] + sB1[col + 1], 0.f));
                v1.x = to_tf32(fmaxf(acc[mt][nt][2] + sB1[col], 0.f));
                v1.y = to_tf32(fmaxf(acc[mt][nt][3] + sB1[col + 1], 0.f));
                *(float2*)(sA + r0 * A_STRIDE + col) = v0;
                *(float2*)(sA + (r0 + 8) * A_STRIDE + col) = v1;
            }
        }
        PBAR();   // h1 ready

        // ================= Layer 2 (pipelined A): h1 @ W2, B in regs =========
#pragma unroll
        for (int mt = 0; mt < 2; ++mt)
#pragma unroll
            for (int nt = 0; nt < 4; ++nt)
#pragma unroll
                for (int j = 0; j < 4; ++j) acc[mt][nt][j] = 0.0f;
        {
            uint32_t aa0[2][4], aa1[2][4];
            ldsm4(aa0[0], aBase0);
            ldsm4(aa1[0], aBase1);
#pragma unroll
            for (int kb = 0; kb < 4; ++kb) {
                const int k1 = 2 * kb + 1;
                ldsm4(aa0[1], aBase0 + k1 * 32);
                ldsm4(aa1[1], aBase1 + k1 * 32);
#pragma unroll
                for (int nt = 0; nt < 4; ++nt) {
                    mma16n8k8(acc[0][nt], aa0[0], B2f[(k1 - 1) * 8 + nt * 2], B2f[(k1 - 1) * 8 + nt * 2 + 1]);
                    mma16n8k8(acc[1][nt], aa1[0], B2f[(k1 - 1) * 8 + nt * 2], B2f[(k1 - 1) * 8 + nt * 2 + 1]);
                }
                if (kb < 3) {
                    ldsm4(aa0[0], aBase0 + (k1 + 1) * 32);
                    ldsm4(aa1[0], aBase1 + (k1 + 1) * 32);
                }
#pragma unroll
                for (int nt = 0; nt < 4; ++nt) {
                    mma16n8k8(acc[0][nt], aa0[1], B2f[k1 * 8 + nt * 2], B2f[k1 * 8 + nt * 2 + 1]);
                    mma16n8k8(acc[1][nt], aa1[1], B2f[k1 * 8 + nt * 2], B2f[k1 * 8 + nt * 2 + 1]);
                }
            }
        }
        // relu(acc + b2) -> A cols [64,128)  (disjoint from h1 reads)
#pragma unroll
        for (int mt = 0; mt < 2; ++mt) {
            const int r0 = pairid * 32 + mt * 16 + gg;
#pragma unroll
            for (int nt = 0; nt < 4; ++nt) {
                const int col = nslot * 32 + nt * 8 + t * 2;
                float2 v0, v1;
                v0.x = to_tf32(fmaxf(acc[mt][nt][0] + sB2[col], 0.f));
                v0.y = to_tf32(fmaxf(acc[mt][nt][1] + sB2[col + 1], 0.f));
                v1.x = to_tf32(fmaxf(acc[mt][nt][2] + sB2[col], 0.f));
                v1.y = to_tf32(fmaxf(acc[mt][nt][3] + sB2[col + 1], 0.f));
                *(float2*)(sA + r0 * A_STRIDE + 64 + col) = v0;
                *(float2*)(sA + (r0 + 8) * A_STRIDE + 64 + col) = v1;
            }
        }
        PBAR();   // h2 ready

        // ================= Layer 3 (pipelined): h2 @ W3 from smem ============
#pragma unroll
        for (int mt = 0; mt < 2; ++mt)
#pragma unroll
            for (int nt = 0; nt < 4; ++nt)
#pragma unroll
                for (int j = 0; j < 4; ++j) acc[mt][nt][j] = 0.0f;
        {
            uint32_t aa0[2][4], aa1[2][4], BB[2][8];
            ldsm4(aa0[0], aBase0 + 256);
            ldsm4(aa1[0], aBase1 + 256);
            ldsm4(BB[0],     w3Base0);
            ldsm4(BB[0] + 4, w3Base1);
#pragma unroll
            for (int kb = 0; kb < 4; ++kb) {
                const int k1 = 2 * kb + 1;
                ldsm4(aa0[1], aBase0 + 256 + k1 * 32);
                ldsm4(aa1[1], aBase1 + 256 + k1 * 32);
                ldsm4(BB[1],     w3Base0 + k1 * 32);
                ldsm4(BB[1] + 4, w3Base1 + k1 * 32);
#pragma unroll
                for (int nt = 0; nt < 4; ++nt) {
                    mma16n8k8(acc[0][nt], aa0[0], BB[0][nt * 2], BB[0][nt * 2 + 1]);
                    mma16n8k8(acc[1][nt], aa1[0], BB[0][nt * 2], BB[0][nt * 2 + 1]);
                }
                if (kb < 3) {
                    ldsm4(aa0[0], aBase0 + 256 + (k1 + 1) * 32);
                    ldsm4(aa1[0], aBase1 + 256 + (k1 + 1) * 32);
                    ldsm4(BB[0],     w3Base0 + (k1 + 1) * 32);
                    ldsm4(BB[0] + 4, w3Base1 + (k1 + 1) * 32);
                }
#pragma unroll
                for (int nt = 0; nt < 4; ++nt) {
                    mma16n8k8(acc[0][nt], aa0[1], BB[1][nt * 2], BB[1][nt * 2 + 1]);
                    mma16n8k8(acc[1][nt], aa1[1], BB[1][nt * 2], BB[1][nt * 2 + 1]);
                }
            }
        }

        // ---- layer 4 epilogue ----
        {
            float pr[2][2];
            pr[0][0] = pr[0][1] = pr[1][0] = pr[1][1] = 0.0f;
#pragma unroll
            for (int mt = 0; mt < 2; ++mt)
#pragma unroll
                for (int nt = 0; nt < 4; ++nt) {
                    const int col = nslot * 32 + nt * 8 + t * 2;
                    pr[mt][0] = fmaf(fmaxf(acc[mt][nt][0] + sB3[col], 0.f),     sW4[col],     pr[mt][0]);
                    pr[mt][0] = fmaf(fmaxf(acc[mt][nt][1] + sB3[col + 1], 0.f), sW4[col + 1], pr[mt][0]);
                    pr[mt][1] = fmaf(fmaxf(acc[mt][nt][2] + sB3[col], 0.f),     sW4[col],     pr[mt][1]);
                    pr[mt][1] = fmaf(fmaxf(acc[mt][nt][3] + sB3[col + 1], 0.f), sW4[col + 1], pr[mt][1]);
                }
#pragma unroll
            for (int mt = 0; mt < 2; ++mt) {
                pr[mt][0] += __shfl_xor_sync(0xffffffffu, pr[mt][0], 1);
                pr[mt][0] += __shfl_xor_sync(0xffffffffu, pr[mt][0], 2);
                pr[mt][1] += __shfl_xor_sync(0xffffffffu, pr[mt][1], 1);
                pr[mt][1] += __shfl_xor_sync(0xffffffffu, pr[mt][1], 2);
                if (t == 0) {
                    const int lr = mt * 16 + gg;                 // local row 0..31
                    sPart[pairid * 64 + nslot * 32 + lr] = pr[mt][0];
                    sPart[pairid * 64 + nslot * 32 + lr + 8] = pr[mt][1];
                }
            }
        }
        PBAR();   // sPart halves ready; pair's L3 A-reads done
        if (gtid < 32)
            out[p0 + gtid] = sPart[pairid * 64 + gtid] + sPart[pairid * 64 + 32 + gtid] + b4v;
    }
}

// ---------------------------------------------------------------------------
// Launch
// ---------------------------------------------------------------------------
extern "C" void kernel_launch(void* const* d_in, const int* in_sizes, int n_in,
                              void* d_out, int out_size) {
    const float* features = (const float*)d_in[0];
    const float* points   = (const float*)d_in[1];
    const float* kmat     = (const float*)d_in[2];
    const float* rtm      = (const float*)d_in[3];
    const float* Bg       = (const float*)d_in[4];
    const float* W1 = (const float*)d_in[5];
    const float* b1 = (const float*)d_in[6];
    const float* W2 = (const float*)d_in[7];
    const float* b2 = (const float*)d_in[8];
    const float* W3 = (const float*)d_in[9];
    const float* b3 = (const float*)d_in[10];
    const float* W4 = (const float*)d_in[11];
    const float* b4 = (const float*)d_in[12];

    dim3 tb(32, 32);
    dim3 tg(3136 / 32, CHN / 32, BATCH);
    transpose_kernel<<<tg, tb>>>(features, W1, W2, W3);

    cudaFuncSetAttribute(decoder_kernel,
                         cudaFuncAttributeMaxDynamicSharedMemorySize, SMEM_TOTAL);
    decoder_kernel<<<GRID_CTAS, NTHREADS, SMEM_TOTAL>>>(
        points, kmat, rtm, Bg, b1, b2, b3, W4, b4, (float*)d_out);
}